// round 3
// baseline (speedup 1.0000x reference)
#include <cuda_runtime.h>
#include <cstddef>

#define NN   100000
#define EE   1600000
#define DINC 128
#define DHC  128
#define DOUTC 64

// ---------------- scratch (no allocations allowed) ----------------
__device__ int   g_deg[NN];
__device__ float g_dinv[NN];
__device__ int   g_rowptr[NN + 1];
__device__ int   g_cursor[NN];
__device__ int   g_col[EE];      // src node per CSR slot (grouped by dst)
__device__ float g_wgt[EE];      // dinv[src]*dinv[dst] per slot
__device__ float g_bufA[(size_t)NN * DHC];
__device__ float g_bufB[(size_t)NN * DHC];

// ---------------- graph build ----------------
__global__ void init_deg_kernel() {
    int i = blockIdx.x * blockDim.x + threadIdx.x;
    if (i < NN) g_deg[i] = 1;   // self loop
}

__global__ void count_deg_kernel(const int* __restrict__ dst) {
    int e = blockIdx.x * blockDim.x + threadIdx.x;
    if (e < EE) atomicAdd(&g_deg[dst[e]], 1);
}

__global__ void dinv_kernel() {
    int i = blockIdx.x * blockDim.x + threadIdx.x;
    if (i < NN) g_dinv[i] = rsqrtf((float)g_deg[i]);
}

// Single-block exclusive scan of indegree (deg-1) -> rowptr, cursor
__global__ void scan_kernel() {
    __shared__ int warp_sums[32];
    int tid  = threadIdx.x;
    int lane = tid & 31;
    int wid  = tid >> 5;
    int carry = 0;
    for (int base = 0; base < NN; base += 1024) {
        int i = base + tid;
        int v = (i < NN) ? (g_deg[i] - 1) : 0;
        // inclusive warp scan
        int x = v;
        #pragma unroll
        for (int o = 1; o < 32; o <<= 1) {
            int y = __shfl_up_sync(0xFFFFFFFFu, x, o);
            if (lane >= o) x += y;
        }
        if (lane == 31) warp_sums[wid] = x;
        __syncthreads();
        if (wid == 0) {
            int s = warp_sums[lane];
            #pragma unroll
            for (int o = 1; o < 32; o <<= 1) {
                int y = __shfl_up_sync(0xFFFFFFFFu, s, o);
                if (lane >= o) s += y;
            }
            warp_sums[lane] = s;  // inclusive scan of warp totals
        }
        __syncthreads();
        int warp_off  = (wid == 0) ? 0 : warp_sums[wid - 1];
        int excl      = carry + warp_off + (x - v);
        if (i < NN) { g_rowptr[i] = excl; g_cursor[i] = excl; }
        int tile_tot  = warp_sums[31];
        carry += tile_tot;
        __syncthreads();
    }
    if (tid == 0) g_rowptr[NN] = carry;   // == EE
}

__global__ void fill_csr_kernel(const int* __restrict__ src, const int* __restrict__ dst) {
    int e = blockIdx.x * blockDim.x + threadIdx.x;
    if (e < EE) {
        int s = src[e], d = dst[e];
        int slot = atomicAdd(&g_cursor[d], 1);
        g_col[slot] = s;
        g_wgt[slot] = g_dinv[s] * g_dinv[d];
    }
}

// ---------------- SGEMM: C[N,BN] = A[N,128] @ W[128,BN] ----------------
// BM=128, BK=8, 256 threads, thread tile TM=8 x TN (8 or 4)
template <int BN, int TN>
__global__ void gemm_kernel(const float* __restrict__ A,
                            const float* __restrict__ W,
                            float* __restrict__ C) {
    constexpr int BM = 128, BK = 8, TM = 8;
    static_assert(BN / TN == 16, "16 threads in N dim");
    __shared__ float As[BK][BM + 4];   // +4 pad: conflict-free transposed store
    __shared__ float Bs[BK][BN];

    const int tid  = threadIdx.x;             // 0..255
    const int trow = tid / 16;                // 0..15
    const int tcol = tid % 16;                // 0..15
    const int rowBase = blockIdx.x * BM;

    float acc[TM][TN];
    #pragma unroll
    for (int m = 0; m < TM; m++)
        #pragma unroll
        for (int n = 0; n < TN; n++) acc[m][n] = 0.0f;

    const int aRow = tid >> 1;
    const int aCol = (tid & 1) * 4;
    constexpr int BCNT = BK * BN / 4;         // float4 count for B tile
    const int bRow = tid / (BN / 4);
    const int bCol = (tid % (BN / 4)) * 4;

    for (int k0 = 0; k0 < DINC; k0 += BK) {
        float4 av = make_float4(0.f, 0.f, 0.f, 0.f);
        int gr = rowBase + aRow;
        if (gr < NN) av = *(const float4*)(A + (size_t)gr * DINC + k0 + aCol);
        As[aCol + 0][aRow] = av.x;
        As[aCol + 1][aRow] = av.y;
        As[aCol + 2][aRow] = av.z;
        As[aCol + 3][aRow] = av.w;
        if (tid < BCNT) {
            float4 bv = *(const float4*)(W + (size_t)(k0 + bRow) * BN + bCol);
            *(float4*)&Bs[bRow][bCol] = bv;
        }
        __syncthreads();
        #pragma unroll
        for (int k = 0; k < BK; k++) {
            float ra[TM], rb[TN];
            #pragma unroll
            for (int m = 0; m < TM; m++) ra[m] = As[k][trow * TM + m];
            #pragma unroll
            for (int n = 0; n < TN; n++) rb[n] = Bs[k][tcol * TN + n];
            #pragma unroll
            for (int m = 0; m < TM; m++)
                #pragma unroll
                for (int n = 0; n < TN; n++) acc[m][n] += ra[m] * rb[n];
        }
        __syncthreads();
    }

    #pragma unroll
    for (int m = 0; m < TM; m++) {
        int r = rowBase + trow * TM + m;
        if (r < NN) {
            #pragma unroll
            for (int v = 0; v < TN; v += 4) {
                float4 o = make_float4(acc[m][v], acc[m][v + 1], acc[m][v + 2], acc[m][v + 3]);
                *(float4*)(C + (size_t)r * BN + tcol * TN + v) = o;
            }
        }
    }
}

// ---------------- Aggregation: warp per destination node (gather) ----------------
template <int D, bool RELU>
__global__ void agg_kernel(const float* __restrict__ hW,
                           const float* __restrict__ bias,
                           float* __restrict__ out) {
    constexpr int V = D / 32;                 // floats per lane (4 or 2)
    int gw   = (blockIdx.x * blockDim.x + threadIdx.x) >> 5;
    int lane = threadIdx.x & 31;
    if (gw >= NN) return;

    float di = g_dinv[gw];
    float acc[V];
    {   // self loop: weight = dinv^2
        float w = di * di;
        const float* p = hW + (size_t)gw * D + lane * V;
        if (V == 4) {
            float4 r = *(const float4*)p;
            acc[0] = w * r.x; acc[1] = w * r.y; acc[2] = w * r.z; acc[3] = w * r.w;
        } else {
            float2 r = *(const float2*)p;
            acc[0] = w * r.x; acc[1] = w * r.y;
        }
    }
    int beg = g_rowptr[gw];
    int end = g_rowptr[gw + 1];
    for (int j = beg; j < end; j++) {
        int   s = g_col[j];
        float w = g_wgt[j];
        const float* p = hW + (size_t)s * D + lane * V;
        if (V == 4) {
            float4 r = *(const float4*)p;
            acc[0] += w * r.x; acc[1] += w * r.y; acc[2] += w * r.z; acc[3] += w * r.w;
        } else {
            float2 r = *(const float2*)p;
            acc[0] += w * r.x; acc[1] += w * r.y;
        }
    }
    // bias (+relu), vectorized store
    float* po = out + (size_t)gw * D + lane * V;
    if (V == 4) {
        float4 b = *(const float4*)(bias + lane * 4);
        float4 o;
        o.x = acc[0] + b.x; o.y = acc[1] + b.y; o.z = acc[2] + b.z; o.w = acc[3] + b.w;
        if (RELU) {
            o.x = fmaxf(o.x, 0.f); o.y = fmaxf(o.y, 0.f);
            o.z = fmaxf(o.z, 0.f); o.w = fmaxf(o.w, 0.f);
        }
        *(float4*)po = o;
    } else {
        float2 b = *(const float2*)(bias + lane * 2);
        float2 o;
        o.x = acc[0] + b.x; o.y = acc[1] + b.y;
        if (RELU) { o.x = fmaxf(o.x, 0.f); o.y = fmaxf(o.y, 0.f); }
        *(float2*)po = o;
    }
}

// ---------------- launch ----------------
extern "C" void kernel_launch(void* const* d_in, const int* in_sizes, int n_in,
                              void* d_out, int out_size) {
    const float* x  = (const float*)d_in[0];
    const float* W0 = (const float*)d_in[1];
    const float* b0 = (const float*)d_in[2];
    const float* W1 = (const float*)d_in[3];
    const float* b1 = (const float*)d_in[4];
    const float* W2 = (const float*)d_in[5];
    const float* b2 = (const float*)d_in[6];
    const int*  src = (const int*)d_in[7];
    const int*  dst = (const int*)d_in[8];
    float* out = (float*)d_out;

    float *bufA = nullptr, *bufB = nullptr;
    cudaGetSymbolAddress((void**)&bufA, g_bufA);
    cudaGetSymbolAddress((void**)&bufB, g_bufB);

    const int TPB = 256;
    const int nodeBlocks = (NN + TPB - 1) / TPB;
    const int edgeBlocks = (EE + TPB - 1) / TPB;
    const int gemmBlocks = (NN + 127) / 128;
    const int aggBlocks  = (NN * 32 + TPB - 1) / TPB;  // warp per node

    // build normalized CSR
    init_deg_kernel<<<nodeBlocks, TPB>>>();
    count_deg_kernel<<<edgeBlocks, TPB>>>(dst);
    dinv_kernel<<<nodeBlocks, TPB>>>();
    scan_kernel<<<1, 1024>>>();
    fill_csr_kernel<<<edgeBlocks, TPB>>>(src, dst);

    // layer 0: relu(agg(x@W0) + b0)
    gemm_kernel<128, 8><<<gemmBlocks, TPB>>>(x, W0, bufA);
    agg_kernel<128, true><<<aggBlocks, TPB>>>(bufA, b0, bufB);
    // layer 1
    gemm_kernel<128, 8><<<gemmBlocks, TPB>>>(bufB, W1, bufA);
    agg_kernel<128, true><<<aggBlocks, TPB>>>(bufA, b1, bufB);
    // layer 2 (no relu) -> d_out
    gemm_kernel<64, 4><<<gemmBlocks, TPB>>>(bufB, W2, bufA);
    agg_kernel<64, false><<<aggBlocks, TPB>>>(bufA, b2, out);
}

// round 4
// speedup vs baseline: 1.1389x; 1.1389x over previous
#include <cuda_runtime.h>
#include <cstdint>
#include <cstddef>

#define NN   100000
#define EE   1600000
#define DINC 128
#define DHC  128
#define DOUTC 64

// ---------------- scratch (no allocations allowed) ----------------
__device__ int   g_deg[NN];
__device__ float g_dinv[NN];
__device__ int   g_rowptr[NN + 1];
__device__ int   g_cursor[NN];
__device__ int   g_col[EE];      // src node per CSR slot (grouped by dst)
__device__ float g_wgt[EE];      // dinv[src]*dinv[dst] per slot
__device__ float g_bufA[(size_t)NN * DHC];
__device__ float g_bufB[(size_t)NN * DHC];

#define SCAN_TPB 1024
#define SCAN_NBLK ((NN + SCAN_TPB - 1) / SCAN_TPB)   // 98
__device__ int g_bsum[128];

// ---------------- graph build ----------------
__global__ void init_deg_kernel() {
    int i = blockIdx.x * blockDim.x + threadIdx.x;
    if (i < NN) g_deg[i] = 1;   // self loop
}

__global__ void count_deg_kernel(const int* __restrict__ dst) {
    int e = blockIdx.x * blockDim.x + threadIdx.x;
    if (e < EE) atomicAdd(&g_deg[dst[e]], 1);
}

__global__ void dinv_kernel() {
    int i = blockIdx.x * blockDim.x + threadIdx.x;
    if (i < NN) g_dinv[i] = rsqrtf((float)g_deg[i]);
}

// ---- decoupled scan: per-block local exclusive scan + block totals ----
__global__ void scan_local_kernel() {
    __shared__ int ws[32];
    int tid  = threadIdx.x;
    int lane = tid & 31;
    int wid  = tid >> 5;
    int i = blockIdx.x * SCAN_TPB + tid;
    int v = (i < NN) ? (g_deg[i] - 1) : 0;
    int x = v;
    #pragma unroll
    for (int o = 1; o < 32; o <<= 1) {
        int y = __shfl_up_sync(0xFFFFFFFFu, x, o);
        if (lane >= o) x += y;
    }
    if (lane == 31) ws[wid] = x;
    __syncthreads();
    if (wid == 0) {
        int s = ws[lane];
        #pragma unroll
        for (int o = 1; o < 32; o <<= 1) {
            int y = __shfl_up_sync(0xFFFFFFFFu, s, o);
            if (lane >= o) s += y;
        }
        ws[lane] = s;
    }
    __syncthreads();
    int excl = (wid ? ws[wid - 1] : 0) + x - v;
    if (i < NN) g_rowptr[i] = excl;                 // local exclusive scan
    if (tid == 0) g_bsum[blockIdx.x] = ws[31];      // block total
}

__global__ void scan_block_kernel() {   // 1 block, 128 threads >= 98 partials
    __shared__ int wsum[4];
    int t = threadIdx.x, lane = t & 31, wid = t >> 5;
    int v = (t < SCAN_NBLK) ? g_bsum[t] : 0;
    int x = v;
    #pragma unroll
    for (int o = 1; o < 32; o <<= 1) {
        int y = __shfl_up_sync(0xFFFFFFFFu, x, o);
        if (lane >= o) x += y;
    }
    if (lane == 31) wsum[wid] = x;
    __syncthreads();
    if (t == 0) {
        int a = 0;
        #pragma unroll
        for (int k = 0; k < 4; k++) { int s = wsum[k]; wsum[k] = a; a += s; }
    }
    __syncthreads();
    int excl = wsum[wid] + x - v;
    if (t < SCAN_NBLK) g_bsum[t] = excl;
}

__global__ void scan_add_kernel() {
    int i = blockIdx.x * blockDim.x + threadIdx.x;
    if (i < NN) {
        int r = g_rowptr[i] + g_bsum[i >> 10];
        g_rowptr[i] = r;
        g_cursor[i] = r;
    }
    if (i == 0) g_rowptr[NN] = EE;
}

__global__ void fill_csr_kernel(const int* __restrict__ src, const int* __restrict__ dst) {
    int e = blockIdx.x * blockDim.x + threadIdx.x;
    if (e < EE) {
        int s = src[e], d = dst[e];
        int slot = atomicAdd(&g_cursor[d], 1);
        g_col[slot] = s;
        g_wgt[slot] = g_dinv[s] * g_dinv[d];
    }
}

// ---------------- 3xTF32 tensor-core GEMM ----------------
// C[N,BN] = A[N,128] @ W[128,BN], fp32-accurate via hi/lo tf32 split.
__device__ __forceinline__ uint32_t f2tf(float f) {
    uint32_t u;
    asm("cvt.rna.tf32.f32 %0, %1;" : "=r"(u) : "f"(f));
    return u;
}

__device__ __forceinline__ void mma8(float* c, const uint32_t* a, const uint32_t* b) {
    asm volatile(
        "mma.sync.aligned.m16n8k8.row.col.f32.tf32.tf32.f32 "
        "{%0,%1,%2,%3}, {%4,%5,%6,%7}, {%8,%9}, {%0,%1,%2,%3};"
        : "+f"(c[0]), "+f"(c[1]), "+f"(c[2]), "+f"(c[3])
        : "r"(a[0]), "r"(a[1]), "r"(a[2]), "r"(a[3]), "r"(b[0]), "r"(b[1]));
}

template <int BN>
__global__ void __launch_bounds__(256)
gemm_tf32_kernel(const float* __restrict__ A,
                 const float* __restrict__ W,
                 float* __restrict__ C) {
    constexpr int BM = 128, BK = 16, BKP = 20, BNP = BN + 8;
    constexpr int WN = BN / 2;       // warp tile in N (2 warps across N)
    constexpr int NT = WN / 8;       // 8 (BN=128) or 4 (BN=64)
    constexpr int BROWF4 = BN / 4;   // float4s per B row

    __shared__ uint32_t Ah[BM][BKP], Al[BM][BKP];
    __shared__ uint32_t Bh[BK][BNP], Bl[BK][BNP];

    const int tid  = threadIdx.x;
    const int lane = tid & 31;
    const int warp = tid >> 5;
    const int wm = (warp & 3) * 32;       // 4 warps in M
    const int wn = (warp >> 2) * WN;      // 2 warps in N
    const int rowBase = blockIdx.x * BM;
    const int g  = lane >> 2;             // "groupID"
    const int tg = lane & 3;              // thread-in-group

    float acc[2][NT][4];
    #pragma unroll
    for (int mt = 0; mt < 2; mt++)
        #pragma unroll
        for (int nt = 0; nt < NT; nt++)
            #pragma unroll
            for (int q = 0; q < 4; q++) acc[mt][nt][q] = 0.0f;

    for (int k0 = 0; k0 < DINC; k0 += BK) {
        // ---- stage A tile (128 x 16), 512 float4, 2 per thread ----
        #pragma unroll
        for (int l = 0; l < 2; l++) {
            int i  = tid + l * 256;
            int r  = i >> 2;
            int c4 = i & 3;
            float4 v = make_float4(0.f, 0.f, 0.f, 0.f);
            int gr = rowBase + r;
            if (gr < NN) v = *(const float4*)(A + (size_t)gr * DINC + k0 + c4 * 4);
            uint32_t h0 = f2tf(v.x), h1 = f2tf(v.y), h2 = f2tf(v.z), h3 = f2tf(v.w);
            uint32_t l0 = f2tf(v.x - __uint_as_float(h0));
            uint32_t l1 = f2tf(v.y - __uint_as_float(h1));
            uint32_t l2 = f2tf(v.z - __uint_as_float(h2));
            uint32_t l3 = f2tf(v.w - __uint_as_float(h3));
            *(uint4*)&Ah[r][c4 * 4] = make_uint4(h0, h1, h2, h3);
            *(uint4*)&Al[r][c4 * 4] = make_uint4(l0, l1, l2, l3);
        }
        // ---- stage B tile (16 x BN) ----
        #pragma unroll
        for (int l = 0; l < (BK * BROWF4 + 255) / 256; l++) {
            int i = tid + l * 256;
            if (BK * BROWF4 % 256 == 0 || i < BK * BROWF4) {
                int br = i / BROWF4;
                int c4 = i % BROWF4;
                float4 v = *(const float4*)(W + (size_t)(k0 + br) * BN + c4 * 4);
                uint32_t h0 = f2tf(v.x), h1 = f2tf(v.y), h2 = f2tf(v.z), h3 = f2tf(v.w);
                uint32_t l0 = f2tf(v.x - __uint_as_float(h0));
                uint32_t l1 = f2tf(v.y - __uint_as_float(h1));
                uint32_t l2 = f2tf(v.z - __uint_as_float(h2));
                uint32_t l3 = f2tf(v.w - __uint_as_float(h3));
                *(uint4*)&Bh[br][c4 * 4] = make_uint4(h0, h1, h2, h3);
                *(uint4*)&Bl[br][c4 * 4] = make_uint4(l0, l1, l2, l3);
            }
        }
        __syncthreads();

        #pragma unroll
        for (int ks = 0; ks < 2; ks++) {
            // A fragments (m16k8 tf32, row-major):
            // a0=(g,t) a1=(g+8,t) a2=(g,t+4) a3=(g+8,t+4)
            uint32_t ah[2][4], al[2][4];
            #pragma unroll
            for (int mt = 0; mt < 2; mt++) {
                int r = wm + mt * 16 + g;
                int c = ks * 8 + tg;
                ah[mt][0] = Ah[r][c];     ah[mt][1] = Ah[r + 8][c];
                ah[mt][2] = Ah[r][c + 4]; ah[mt][3] = Ah[r + 8][c + 4];
                al[mt][0] = Al[r][c];     al[mt][1] = Al[r + 8][c];
                al[mt][2] = Al[r][c + 4]; al[mt][3] = Al[r + 8][c + 4];
            }
            #pragma unroll
            for (int nt = 0; nt < NT; nt++) {
                // B fragments (k8n8 tf32, "col"): b0=(k=t,n=g) b1=(k=t+4,n=g)
                int bc = wn + nt * 8 + g;
                int br = ks * 8 + tg;
                uint32_t bh[2] = { Bh[br][bc], Bh[br + 4][bc] };
                uint32_t bl[2] = { Bl[br][bc], Bl[br + 4][bc] };
                #pragma unroll
                for (int mt = 0; mt < 2; mt++) {
                    mma8(acc[mt][nt], ah[mt], bh);
                    mma8(acc[mt][nt], ah[mt], bl);
                    mma8(acc[mt][nt], al[mt], bh);
                }
            }
        }
        __syncthreads();
    }

    // epilogue: c0,c1 -> (row g, cols 2t,2t+1); c2,c3 -> (row g+8)
    #pragma unroll
    for (int mt = 0; mt < 2; mt++) {
        int r0 = rowBase + wm + mt * 16 + g;
        #pragma unroll
        for (int nt = 0; nt < NT; nt++) {
            int col = wn + nt * 8 + tg * 2;
            if (r0 < NN)
                *(float2*)(C + (size_t)r0 * BN + col) = make_float2(acc[mt][nt][0], acc[mt][nt][1]);
            if (r0 + 8 < NN)
                *(float2*)(C + (size_t)(r0 + 8) * BN + col) = make_float2(acc[mt][nt][2], acc[mt][nt][3]);
        }
    }
}

// ---------------- Aggregation: warp per destination node (gather) ----------------
template <int D, bool RELU>
__global__ void agg_kernel(const float* __restrict__ hW,
                           const float* __restrict__ bias,
                           float* __restrict__ out) {
    constexpr int V = D / 32;                 // floats per lane (4 or 2)
    int gw   = (blockIdx.x * blockDim.x + threadIdx.x) >> 5;
    int lane = threadIdx.x & 31;
    if (gw >= NN) return;

    float di = g_dinv[gw];
    float acc[V];
    {   // self loop: weight = dinv^2
        float w = di * di;
        const float* p = hW + (size_t)gw * D + lane * V;
        if (V == 4) {
            float4 r = *(const float4*)p;
            acc[0] = w * r.x; acc[1] = w * r.y; acc[2] = w * r.z; acc[3] = w * r.w;
        } else {
            float2 r = *(const float2*)p;
            acc[0] = w * r.x; acc[1] = w * r.y;
        }
    }
    int j   = g_rowptr[gw];
    int end = g_rowptr[gw + 1];
    // unroll-2: two independent gathers in flight
    for (; j + 2 <= end; j += 2) {
        int   s0 = g_col[j],   s1 = g_col[j + 1];
        float w0 = g_wgt[j],   w1 = g_wgt[j + 1];
        if (V == 4) {
            float4 r0 = *(const float4*)(hW + (size_t)s0 * D + lane * 4);
            float4 r1 = *(const float4*)(hW + (size_t)s1 * D + lane * 4);
            acc[0] += w0 * r0.x; acc[1] += w0 * r0.y; acc[2] += w0 * r0.z; acc[3] += w0 * r0.w;
            acc[0] += w1 * r1.x; acc[1] += w1 * r1.y; acc[2] += w1 * r1.z; acc[3] += w1 * r1.w;
        } else {
            float2 r0 = *(const float2*)(hW + (size_t)s0 * D + lane * 2);
            float2 r1 = *(const float2*)(hW + (size_t)s1 * D + lane * 2);
            acc[0] += w0 * r0.x; acc[1] += w0 * r0.y;
            acc[0] += w1 * r1.x; acc[1] += w1 * r1.y;
        }
    }
    if (j < end) {
        int   s = g_col[j];
        float w = g_wgt[j];
        if (V == 4) {
            float4 r = *(const float4*)(hW + (size_t)s * D + lane * 4);
            acc[0] += w * r.x; acc[1] += w * r.y; acc[2] += w * r.z; acc[3] += w * r.w;
        } else {
            float2 r = *(const float2*)(hW + (size_t)s * D + lane * 2);
            acc[0] += w * r.x; acc[1] += w * r.y;
        }
    }
    float* po = out + (size_t)gw * D + lane * V;
    if (V == 4) {
        float4 b = *(const float4*)(bias + lane * 4);
        float4 o;
        o.x = acc[0] + b.x; o.y = acc[1] + b.y; o.z = acc[2] + b.z; o.w = acc[3] + b.w;
        if (RELU) {
            o.x = fmaxf(o.x, 0.f); o.y = fmaxf(o.y, 0.f);
            o.z = fmaxf(o.z, 0.f); o.w = fmaxf(o.w, 0.f);
        }
        *(float4*)po = o;
    } else {
        float2 b = *(const float2*)(bias + lane * 2);
        float2 o;
        o.x = acc[0] + b.x; o.y = acc[1] + b.y;
        if (RELU) { o.x = fmaxf(o.x, 0.f); o.y = fmaxf(o.y, 0.f); }
        *(float2*)po = o;
    }
}

// ---------------- launch ----------------
extern "C" void kernel_launch(void* const* d_in, const int* in_sizes, int n_in,
                              void* d_out, int out_size) {
    const float* x  = (const float*)d_in[0];
    const float* W0 = (const float*)d_in[1];
    const float* b0 = (const float*)d_in[2];
    const float* W1 = (const float*)d_in[3];
    const float* b1 = (const float*)d_in[4];
    const float* W2 = (const float*)d_in[5];
    const float* b2 = (const float*)d_in[6];
    const int*  src = (const int*)d_in[7];
    const int*  dst = (const int*)d_in[8];
    float* out = (float*)d_out;

    float *bufA = nullptr, *bufB = nullptr;
    cudaGetSymbolAddress((void**)&bufA, g_bufA);
    cudaGetSymbolAddress((void**)&bufB, g_bufB);

    const int TPB = 256;
    const int nodeBlocks = (NN + TPB - 1) / TPB;
    const int edgeBlocks = (EE + TPB - 1) / TPB;
    const int gemmBlocks = (NN + 127) / 128;
    const int aggBlocks  = (NN * 32 + TPB - 1) / TPB;  // warp per node

    // build normalized CSR
    init_deg_kernel<<<nodeBlocks, TPB>>>();
    count_deg_kernel<<<edgeBlocks, TPB>>>(dst);
    dinv_kernel<<<nodeBlocks, TPB>>>();
    scan_local_kernel<<<SCAN_NBLK, SCAN_TPB>>>();
    scan_block_kernel<<<1, 128>>>();
    scan_add_kernel<<<(NN + 1023) / 1024, 1024>>>();
    fill_csr_kernel<<<edgeBlocks, TPB>>>(src, dst);

    // layer 0: relu(agg(x@W0) + b0)
    gemm_tf32_kernel<128><<<gemmBlocks, TPB>>>(x, W0, bufA);
    agg_kernel<128, true><<<aggBlocks, TPB>>>(bufA, b0, bufB);
    // layer 1
    gemm_tf32_kernel<128><<<gemmBlocks, TPB>>>(bufB, W1, bufA);
    agg_kernel<128, true><<<aggBlocks, TPB>>>(bufA, b1, bufB);
    // layer 2 (no relu) -> d_out
    gemm_tf32_kernel<64><<<gemmBlocks, TPB>>>(bufB, W2, bufA);
    agg_kernel<64, false><<<aggBlocks, TPB>>>(bufA, b2, out);
}

// round 6
// speedup vs baseline: 1.5362x; 1.3488x over previous
#include <cuda_runtime.h>
#include <cuda_fp16.h>
#include <cstdint>
#include <cstddef>

#define NN   100000
#define EE   1600000
#define DINC 128
#define DHC  128
#define DOUTC 64

// ---------------- scratch (no allocations allowed) ----------------
__device__ int   g_deg[NN];
__device__ float g_dinv[NN];
__device__ int   g_rowptr[NN + 1];
__device__ int   g_cursor[NN];
__device__ int   g_col[EE];      // src node per CSR slot (grouped by dst)
__device__ float g_wgt[EE];      // dinv[src]*dinv[dst] per slot
__device__ float g_bufA[(size_t)NN * DHC];
__device__ float g_bufB[(size_t)NN * DHC];

#define SCAN_TPB 1024
#define SCAN_NBLK ((NN + SCAN_TPB - 1) / SCAN_TPB)   // 98
__device__ int g_bsum[128];

// ---------------- graph build ----------------
__global__ void count_deg_kernel(const int* __restrict__ dst) {
    int e = blockIdx.x * blockDim.x + threadIdx.x;
    if (e < EE) atomicAdd(&g_deg[dst[e]], 1);
}

// per-block local exclusive scan of edge-indegree + block totals + dinv
__global__ void scan_local_kernel() {
    __shared__ int ws[32];
    int tid  = threadIdx.x;
    int lane = tid & 31;
    int wid  = tid >> 5;
    int i = blockIdx.x * SCAN_TPB + tid;
    int v = (i < NN) ? g_deg[i] : 0;
    if (i < NN) g_dinv[i] = rsqrtf((float)(v + 1));   // +1 self loop
    int x = v;
    #pragma unroll
    for (int o = 1; o < 32; o <<= 1) {
        int y = __shfl_up_sync(0xFFFFFFFFu, x, o);
        if (lane >= o) x += y;
    }
    if (lane == 31) ws[wid] = x;
    __syncthreads();
    if (wid == 0) {
        int s = ws[lane];
        #pragma unroll
        for (int o = 1; o < 32; o <<= 1) {
            int y = __shfl_up_sync(0xFFFFFFFFu, s, o);
            if (lane >= o) s += y;
        }
        ws[lane] = s;
    }
    __syncthreads();
    int excl = (wid ? ws[wid - 1] : 0) + x - v;
    if (i < NN) g_rowptr[i] = excl;
    if (tid == 0) g_bsum[blockIdx.x] = ws[31];
}

__global__ void scan_block_kernel() {   // 1 block, 128 threads >= 98 partials
    __shared__ int wsum[4];
    int t = threadIdx.x, lane = t & 31, wid = t >> 5;
    int v = (t < SCAN_NBLK) ? g_bsum[t] : 0;
    int x = v;
    #pragma unroll
    for (int o = 1; o < 32; o <<= 1) {
        int y = __shfl_up_sync(0xFFFFFFFFu, x, o);
        if (lane >= o) x += y;
    }
    if (lane == 31) wsum[wid] = x;
    __syncthreads();
    if (t == 0) {
        int a = 0;
        #pragma unroll
        for (int k = 0; k < 4; k++) { int s = wsum[k]; wsum[k] = a; a += s; }
    }
    __syncthreads();
    int excl = wsum[wid] + x - v;
    if (t < SCAN_NBLK) g_bsum[t] = excl;
}

__global__ void scan_add_kernel() {
    int i = blockIdx.x * blockDim.x + threadIdx.x;
    if (i < NN) {
        int r = g_rowptr[i] + g_bsum[i >> 10];
        g_rowptr[i] = r;
        g_cursor[i] = r;
    }
    if (i == 0) g_rowptr[NN] = EE;
}

__global__ void fill_csr_kernel(const int* __restrict__ src, const int* __restrict__ dst) {
    int e = blockIdx.x * blockDim.x + threadIdx.x;
    if (e < EE) {
        int s = src[e], d = dst[e];
        int slot = atomicAdd(&g_cursor[d], 1);
        g_col[slot] = s;
        g_wgt[slot] = g_dinv[s] * g_dinv[d];
    }
}

// ================= fp16-split mma.sync GEMM =================
// C[N,BN] = A[N,128] @ W[128,BN], fp32-grade: x = hi + lo (fp16 each),
// D = Ah*Bh + Ah*Bl + Al*Bh accumulated in fp32 by HMMA.16816.
__device__ __forceinline__ uint32_t s2u(const void* p) {
    uint32_t a;
    asm("{ .reg .u64 t; cvta.to.shared.u64 t, %1; cvt.u32.u64 %0, t; }" : "=r"(a) : "l"(p));
    return a;
}

#define LDSM4(r, a)                                                            \
    asm volatile("ldmatrix.sync.aligned.m8n8.x4.shared.b16 {%0,%1,%2,%3}, [%4];" \
                 : "=r"((r)[0]), "=r"((r)[1]), "=r"((r)[2]), "=r"((r)[3])      \
                 : "r"(a))

__device__ __forceinline__ void mma16816(float* c, const uint32_t* a, const uint32_t* b) {
    asm volatile(
        "mma.sync.aligned.m16n8k16.row.col.f32.f16.f16.f32 "
        "{%0,%1,%2,%3}, {%4,%5,%6,%7}, {%8,%9}, {%0,%1,%2,%3};"
        : "+f"(c[0]), "+f"(c[1]), "+f"(c[2]), "+f"(c[3])
        : "r"(a[0]), "r"(a[1]), "r"(a[2]), "r"(a[3]), "r"(b[0]), "r"(b[1]));
}

__device__ __forceinline__ uint32_t pack2(__half a, __half b) {
    __half2 h = __halves2half2(a, b);
    return *(uint32_t*)&h;
}

// smem tile: rows of KC=64 fp16 + 8 pad halves (row stride 72 halves = 144 B)
template <int BN>
__global__ void __launch_bounds__(256, 2)
gemm_mma_kernel(const float* __restrict__ A, const float* __restrict__ W,
                float* __restrict__ C) {
    constexpr int K = 128, KC = 64, RS = 72;
    constexpr int A_HI = 0;
    constexpr int A_LO = 128 * RS;
    constexpr int B_HI = 2 * 128 * RS;
    constexpr int B_LO = B_HI + BN * RS;
    constexpr int NT = BN / 16;          // n8-tiles per warp (8 or 4)
    constexpr int NP = NT / 2;           // ldmatrix x4 pairs (4 or 2)

    extern __shared__ __half sm[];
    const uint32_t sb = s2u(sm);
    const int tid  = threadIdx.x;
    const int lane = tid & 31;
    const int warp = tid >> 5;
    const int wm = (warp & 3) * 32;
    const int wn = (warp >> 2) * (BN / 2);
    const int rowBase = blockIdx.x * 128;

    float acc[2][NT][4];
    #pragma unroll
    for (int mt = 0; mt < 2; mt++)
        #pragma unroll
        for (int nt = 0; nt < NT; nt++)
            #pragma unroll
            for (int q = 0; q < 4; q++) acc[mt][nt][q] = 0.0f;

    // ldmatrix lane->address maps
    const int aRow = (lane & 7) + ((lane >> 3) & 1) * 8;   // A: r0 rows0-7@k0, r1 rows8-15@k0, r2 rows0-7@k8, r3 rows8-15@k8
    const int aK   = (lane >> 4) * 8;
    const int bN   = (lane & 7) + ((lane >> 4) << 3);      // B: r0 n0-7@k0, r1 n0-7@k8, r2 n8-15@k0, r3 n8-15@k8
    const int bK   = ((lane >> 3) & 1) * 8;

    for (int kc = 0; kc < 2; kc++) {
        // ---- stage A chunk (128 x 64 fp32 -> hi/lo fp16) ----
        #pragma unroll
        for (int l = 0; l < 8; l++) {
            int i = tid + l * 256;           // 2048 float4
            int r = i >> 4;
            int c = (i & 15) * 4;
            float4 v = make_float4(0.f, 0.f, 0.f, 0.f);
            int gr = rowBase + r;
            if (gr < NN) v = *(const float4*)(A + (size_t)gr * K + kc * KC + c);
            __half h0 = __float2half_rn(v.x), h1 = __float2half_rn(v.y);
            __half h2 = __float2half_rn(v.z), h3 = __float2half_rn(v.w);
            __half q0 = __float2half_rn(v.x - __half2float(h0));
            __half q1 = __float2half_rn(v.y - __half2float(h1));
            __half q2 = __float2half_rn(v.z - __half2float(h2));
            __half q3 = __float2half_rn(v.w - __half2float(h3));
            *(uint2*)&sm[A_HI + r * RS + c] = make_uint2(pack2(h0, h1), pack2(h2, h3));
            *(uint2*)&sm[A_LO + r * RS + c] = make_uint2(pack2(q0, q1), pack2(q2, q3));
        }
        // ---- stage B chunk: Bsm[n][k] = W[kc*64+k][n], k0..k0+3 per thread ----
        #pragma unroll
        for (int l = 0; l < BN * KC / 4 / 256; l++) {
            int i  = tid + l * 256;
            int n  = i % BN;                  // consecutive tid -> consecutive n (coalesced)
            int k0 = (i / BN) * 4;
            float v0 = W[(size_t)(kc * KC + k0 + 0) * BN + n];
            float v1 = W[(size_t)(kc * KC + k0 + 1) * BN + n];
            float v2 = W[(size_t)(kc * KC + k0 + 2) * BN + n];
            float v3 = W[(size_t)(kc * KC + k0 + 3) * BN + n];
            __half h0 = __float2half_rn(v0), h1 = __float2half_rn(v1);
            __half h2 = __float2half_rn(v2), h3 = __float2half_rn(v3);
            __half q0 = __float2half_rn(v0 - __half2float(h0));
            __half q1 = __float2half_rn(v1 - __half2float(h1));
            __half q2 = __float2half_rn(v2 - __half2float(h2));
            __half q3 = __float2half_rn(v3 - __half2float(h3));
            *(uint2*)&sm[B_HI + n * RS + k0] = make_uint2(pack2(h0, h1), pack2(h2, h3));
            *(uint2*)&sm[B_LO + n * RS + k0] = make_uint2(pack2(q0, q1), pack2(q2, q3));
        }
        __syncthreads();

        #pragma unroll
        for (int ks = 0; ks < KC / 16; ks++) {
            uint32_t ah[2][4], al[2][4];
            #pragma unroll
            for (int mt = 0; mt < 2; mt++) {
                uint32_t off = (uint32_t)((wm + mt * 16 + aRow) * RS + ks * 16 + aK) * 2;
                LDSM4(ah[mt], sb + A_HI * 2 + off);
                LDSM4(al[mt], sb + A_LO * 2 + off);
            }
            #pragma unroll
            for (int np = 0; np < NP; np++) {
                uint32_t bh[4], bl[4];
                uint32_t off = (uint32_t)((wn + np * 16 + bN) * RS + ks * 16 + bK) * 2;
                LDSM4(bh, sb + B_HI * 2 + off);
                LDSM4(bl, sb + B_LO * 2 + off);
                #pragma unroll
                for (int mt = 0; mt < 2; mt++) {
                    mma16816(acc[mt][np * 2 + 0], ah[mt], &bh[0]);
                    mma16816(acc[mt][np * 2 + 0], ah[mt], &bl[0]);
                    mma16816(acc[mt][np * 2 + 0], al[mt], &bh[0]);
                    mma16816(acc[mt][np * 2 + 1], ah[mt], &bh[2]);
                    mma16816(acc[mt][np * 2 + 1], ah[mt], &bl[2]);
                    mma16816(acc[mt][np * 2 + 1], al[mt], &bh[2]);
                }
            }
        }
        __syncthreads();
    }

    // epilogue: c0,c1 -> (row g, col tg*2..+1); c2,c3 -> (row g+8)
    const int g  = lane >> 2;
    const int tg = lane & 3;
    #pragma unroll
    for (int mt = 0; mt < 2; mt++) {
        int r0 = rowBase + wm + mt * 16 + g;
        #pragma unroll
        for (int nt = 0; nt < NT; nt++) {
            int col = wn + nt * 8 + tg * 2;
            if (r0 < NN)
                *(float2*)(C + (size_t)r0 * BN + col) = make_float2(acc[mt][nt][0], acc[mt][nt][1]);
            if (r0 + 8 < NN)
                *(float2*)(C + (size_t)(r0 + 8) * BN + col) = make_float2(acc[mt][nt][2], acc[mt][nt][3]);
        }
    }
}

// ---------------- Aggregation: warp per destination node (gather) ----------------
template <int D, bool RELU>
__global__ void agg_kernel(const float* __restrict__ hW,
                           const float* __restrict__ bias,
                           float* __restrict__ out) {
    constexpr int V = D / 32;                 // floats per lane (4 or 2)
    int gw   = (blockIdx.x * blockDim.x + threadIdx.x) >> 5;
    int lane = threadIdx.x & 31;
    if (gw >= NN) return;

    float di = g_dinv[gw];
    float acc[V];
    {   // self loop: weight = dinv^2
        float w = di * di;
        const float* p = hW + (size_t)gw * D + lane * V;
        if (V == 4) {
            float4 r = *(const float4*)p;
            acc[0] = w * r.x; acc[1] = w * r.y; acc[2] = w * r.z; acc[3] = w * r.w;
        } else {
            float2 r = *(const float2*)p;
            acc[0] = w * r.x; acc[1] = w * r.y;
        }
    }
    int j   = g_rowptr[gw];
    int end = g_rowptr[gw + 1];
    for (; j + 2 <= end; j += 2) {
        int   s0 = g_col[j],   s1 = g_col[j + 1];
        float w0 = g_wgt[j],   w1 = g_wgt[j + 1];
        if (V == 4) {
            float4 r0 = *(const float4*)(hW + (size_t)s0 * D + lane * 4);
            float4 r1 = *(const float4*)(hW + (size_t)s1 * D + lane * 4);
            acc[0] += w0 * r0.x; acc[1] += w0 * r0.y; acc[2] += w0 * r0.z; acc[3] += w0 * r0.w;
            acc[0] += w1 * r1.x; acc[1] += w1 * r1.y; acc[2] += w1 * r1.z; acc[3] += w1 * r1.w;
        } else {
            float2 r0 = *(const float2*)(hW + (size_t)s0 * D + lane * 2);
            float2 r1 = *(const float2*)(hW + (size_t)s1 * D + lane * 2);
            acc[0] += w0 * r0.x; acc[1] += w0 * r0.y;
            acc[0] += w1 * r1.x; acc[1] += w1 * r1.y;
        }
    }
    if (j < end) {
        int   s = g_col[j];
        float w = g_wgt[j];
        if (V == 4) {
            float4 r = *(const float4*)(hW + (size_t)s * D + lane * 4);
            acc[0] += w * r.x; acc[1] += w * r.y; acc[2] += w * r.z; acc[3] += w * r.w;
        } else {
            float2 r = *(const float2*)(hW + (size_t)s * D + lane * 2);
            acc[0] += w * r.x; acc[1] += w * r.y;
        }
    }
    float* po = out + (size_t)gw * D + lane * V;
    if (V == 4) {
        float4 b = *(const float4*)(bias + lane * 4);
        float4 o;
        o.x = acc[0] + b.x; o.y = acc[1] + b.y; o.z = acc[2] + b.z; o.w = acc[3] + b.w;
        if (RELU) {
            o.x = fmaxf(o.x, 0.f); o.y = fmaxf(o.y, 0.f);
            o.z = fmaxf(o.z, 0.f); o.w = fmaxf(o.w, 0.f);
        }
        *(float4*)po = o;
    } else {
        float2 b = *(const float2*)(bias + lane * 2);
        float2 o;
        o.x = acc[0] + b.x; o.y = acc[1] + b.y;
        if (RELU) { o.x = fmaxf(o.x, 0.f); o.y = fmaxf(o.y, 0.f); }
        *(float2*)po = o;
    }
}

// ---------------- launch ----------------
extern "C" void kernel_launch(void* const* d_in, const int* in_sizes, int n_in,
                              void* d_out, int out_size) {
    const float* x  = (const float*)d_in[0];
    const float* W0 = (const float*)d_in[1];
    const float* b0 = (const float*)d_in[2];
    const float* W1 = (const float*)d_in[3];
    const float* b1 = (const float*)d_in[4];
    const float* W2 = (const float*)d_in[5];
    const float* b2 = (const float*)d_in[6];
    const int*  src = (const int*)d_in[7];
    const int*  dst = (const int*)d_in[8];
    float* out = (float*)d_out;

    float *bufA = nullptr, *bufB = nullptr;
    void* degp = nullptr;
    cudaGetSymbolAddress((void**)&bufA, g_bufA);
    cudaGetSymbolAddress((void**)&bufB, g_bufB);
    cudaGetSymbolAddress(&degp, g_deg);

    // smem: (2*128 + 2*BN) rows * 72 halves * 2B
    const int SMEM128 = (2 * 128 + 2 * 128) * 72 * 2;   // 73728
    const int SMEM64  = (2 * 128 + 2 * 64)  * 72 * 2;   // 55296
    cudaFuncSetAttribute(gemm_mma_kernel<128>,
                         cudaFuncAttributeMaxDynamicSharedMemorySize, SMEM128);
    cudaFuncSetAttribute(gemm_mma_kernel<64>,
                         cudaFuncAttributeMaxDynamicSharedMemorySize, SMEM64);

    const int TPB = 256;
    const int edgeBlocks = (EE + TPB - 1) / TPB;
    const int gemmBlocks = (NN + 127) / 128;
    const int aggBlocks  = (NN * 32 + TPB - 1) / TPB;  // warp per node

    // build normalized CSR
    cudaMemsetAsync(degp, 0, NN * sizeof(int));
    count_deg_kernel<<<edgeBlocks, TPB>>>(dst);
    scan_local_kernel<<<SCAN_NBLK, SCAN_TPB>>>();
    scan_block_kernel<<<1, 128>>>();
    scan_add_kernel<<<(NN + 1023) / 1024, 1024>>>();
    fill_csr_kernel<<<edgeBlocks, TPB>>>(src, dst);

    // layer 0: relu(agg(x@W0) + b0)
    gemm_mma_kernel<128><<<gemmBlocks, TPB, SMEM128>>>(x, W0, bufA);
    agg_kernel<128, true><<<aggBlocks, TPB>>>(bufA, b0, bufB);
    // layer 1
    gemm_mma_kernel<128><<<gemmBlocks, TPB, SMEM128>>>(bufB, W1, bufA);
    agg_kernel<128, true><<<aggBlocks, TPB>>>(bufA, b1, bufB);
    // layer 2 (no relu) -> d_out
    gemm_mma_kernel<64><<<gemmBlocks, TPB, SMEM64>>>(bufB, W2, bufA);
    agg_kernel<64, false><<<aggBlocks, TPB>>>(bufA, b2, out);
}